// round 12
// baseline (speedup 1.0000x reference)
#include <cuda_runtime.h>
#include <cstdint>

#define BB 2
#define DD 512
#define KK 32
#define NN 4096
#define ZSIZE (BB*DD*KK)

typedef unsigned long long ull;

// ---------- device scratch ----------
__device__ float g_Af[DD*KK];            // s^2
__device__ float g_Bf[DD*KK];            // -2 s^2 c
__device__ float g_C[KK];
__device__ float g_S1part[128*KK];
__device__ float g_M2[(size_t)BB*64*DD*KK];  // [b*64+chunk][d][k] 8MB
__device__ float g_SS[BB*64*KK];

// ---------- f32x2 helpers ----------
__device__ __forceinline__ ull pk2(float lo, float hi) {
    ull r; asm("mov.b64 %0, {%1,%2};" : "=l"(r) : "f"(lo), "f"(hi)); return r;
}
__device__ __forceinline__ void upk2(ull v, float& lo, float& hi) {
    asm("mov.b64 {%0,%1}, %2;" : "=f"(lo), "=f"(hi) : "l"(v));
}
__device__ __forceinline__ ull fma2(ull a, ull b, ull c) {
    ull d; asm("fma.rn.f32x2 %0, %1, %2, %3;" : "=l"(d) : "l"(a), "l"(b), "l"(c)); return d;
}
__device__ __forceinline__ void gbar(int id) {
    asm volatile("bar.sync %0, %1;" :: "r"(id), "r"(256) : "memory");
}

// ============ K0: prep — coefficients + C[k]. grid 32 x 512 ============
__global__ __launch_bounds__(512) void prep_kernel(const float* __restrict__ scale,
                                                   const float* __restrict__ cw) {
    const int t = threadIdx.x;
    const int k = blockIdx.x;
    // AB entries: 512 per block, idx = d*32+kk
    {
        int idx = blockIdx.x*512 + t;
        int d2 = idx >> 5, k2 = idx & 31;
        float s = scale[idx];
        float c = cw[k2*DD + d2];
        float s2 = s*s;
        g_Af[idx] = s2;
        g_Bf[idx] = -2.f*s2*c;
    }
    // C[k] for k = bid
    __shared__ float red[512];
    {
        float sv = scale[t*KK + k];
        float cv = cw[k*DD + t];
        red[t] = sv*sv*cv*cv;
    }
    __syncthreads();
    #pragma unroll
    for (int off = 256; off > 0; off >>= 1) {
        if (t < off) red[t] += red[t + off];
        __syncthreads();
    }
    if (t == 0) g_C[k] = red[0];
}

// ============ K1: assign — E-GEMM + softmax -> Q. grid 128 x 1024 ============
// smem: XG [4][2][64][16] 32KB @0 ; Asf 64KB @32768 ; Bsf 64KB @98304
// epilogue alias: Ep [32][512] 64KB @32768 ; Ef [64][32] @98304 ; red @106496
#define K1_XG  0
#define K1_ASF 32768
#define K1_BSF 98304
#define K1_EP  32768
#define K1_EF  98304
#define K1_RED 106496
#define SMEM_K1 163840

__global__ __launch_bounds__(1024) void assign_kernel(const float* __restrict__ X,
                                                      float* __restrict__ out) {
    extern __shared__ unsigned char sm[];
    const int tid  = threadIdx.x;
    const int lane = tid & 31;
    const int w    = tid >> 5;           // 0..31
    const int grp  = w >> 3;             // 0..3
    const int wd   = w & 7;
    const int gt   = tid & 255;
    const int bid  = blockIdx.x;

    const int n0 = bid * 64;
    const int b  = n0 >> 12;

    ull acc[8];
    {
        float* XG  = (float*)(sm + K1_XG);
        float* Asf = (float*)(sm + K1_ASF);
        float* Bsf = (float*)(sm + K1_BSF);

        const float* Xb = X + (size_t)b*DD*NN + (n0 & (NN - 1)) + grp*16;
        float* XGg = XG + grp*2048;

        #pragma unroll
        for (int it = 0; it < 4; it++) {
            ((float4*)Asf)[tid + it*1024] = ((const float4*)g_Af)[tid + it*1024];
            ((float4*)Bsf)[tid + it*1024] = ((const float4*)g_Bf)[tid + it*1024];
        }
        const int sr = gt >> 2, sc = gt & 3;
        float4 xpre = *(const float4*)(Xb + (size_t)sr*NN + sc*4);
        *(float4*)&XGg[sr*16 + sc*4] = xpre;
        __syncthreads();

        #pragma unroll
        for (int i = 0; i < 8; i++) acc[i] = 0ull;

        #pragma unroll 1
        for (int c = 0; c < 8; c++) {
            const float* Xs = XGg + (c & 1)*1024;
            if (c < 7)
                xpre = *(const float4*)(Xb + (size_t)((c+1)*64 + sr)*NN + sc*4);
            const float* Ac = Asf + c*64*KK;
            const float* Bc = Bsf + c*64*KK;
            #pragma unroll
            for (int it = 0; it < 8; it++) {
                int dd = wd + it*8;
                float av = Ac[dd*KK + lane];
                float bv = Bc[dd*KK + lane];
                ull a2 = pk2(av, av), b2 = pk2(bv, bv);
                const float* xr = &Xs[dd*16];
                #pragma unroll
                for (int g = 0; g < 4; g++) {
                    longlong2 xv = *reinterpret_cast<const longlong2*>(xr + g*4);
                    ull x01 = (ull)xv.x, x23 = (ull)xv.y;
                    ull t0 = fma2(a2, x01, b2);
                    acc[2*g]   = fma2(x01, t0, acc[2*g]);
                    ull t1 = fma2(a2, x23, b2);
                    acc[2*g+1] = fma2(x23, t1, acc[2*g+1]);
                }
            }
            if (c < 7)
                *(float4*)&XGg[(1 - (c & 1))*1024 + sr*16 + sc*4] = xpre;
            gbar(1 + grp);
        }
        __syncthreads();        // coeff regions dead
    }

    // ---- single-wave cross-warp E reduce, softmax, Q out ----
    {
        float* Ep  = (float*)(sm + K1_EP);       // [32][512]
        float* Ef  = (float*)(sm + K1_EF);       // [64][32]
        float* red = (float*)(sm + K1_RED);      // [32][33]

        #pragma unroll
        for (int i = 0; i < 8; i++) {
            float lo, hi; upk2(acc[i], lo, hi);
            Ep[w*512 + (2*i  )*KK + lane] = lo;
            Ep[w*512 + (2*i+1)*KK + lane] = hi;
        }
        __syncthreads();
        #pragma unroll
        for (int it = 0; it < 2; it++) {
            int idx = tid + it*1024;             // n*32+k
            int n = idx >> 5, k = idx & 31;
            int gg = n >> 4, nl = n & 15;
            float s = 0.f;
            #pragma unroll
            for (int wdd = 0; wdd < 8; wdd++)
                s += Ep[(gg*8 + wdd)*512 + nl*KK + k];
            Ef[idx] = s;
        }
        __syncthreads();

        float* Qout = out + ZSIZE;
        const float Ck = g_C[lane];
        float s1loc = 0.f;
        #pragma unroll
        for (int i = 0; i < 2; i++) {
            int n = w*2 + i;
            float arg = -0.5f * (Ef[n*KK + lane] + Ck);
            float m = arg;
            #pragma unroll
            for (int off = 16; off; off >>= 1) m = fmaxf(m, __shfl_xor_sync(~0u, m, off));
            float ex = __expf(arg - m);
            float ssum = ex;
            #pragma unroll
            for (int off = 16; off; off >>= 1) ssum += __shfl_xor_sync(~0u, ssum, off);
            float q = ex / ssum;
            Qout[(size_t)(n0 + n)*KK + lane] = q;
            s1loc += q;
        }
        red[w*33 + lane] = s1loc;
        __syncthreads();
        if (w == 0) {
            float s = 0.f;
            #pragma unroll
            for (int i = 0; i < 32; i++) s += red[i*33 + lane];
            g_S1part[bid*KK + lane] = s;
        }
    }
}

// ============ K2: aggregate — M over 64 n, all 512 d. grid 128 x 1024 ============
#define K2_XS 0        // [512][64] 128KB
#define K2_QS 131072   // ull [32][32] 8KB
#define SMEM_K2 139264

__global__ __launch_bounds__(1024) void aggregate_kernel(const float* __restrict__ X,
                                                         const float* __restrict__ out) {
    extern __shared__ unsigned char sm[];
    const int tid  = threadIdx.x;
    const int lane = tid & 31;
    const int w    = tid >> 5;
    const int bid  = blockIdx.x;
    const int n0   = bid * 64;
    const int b    = n0 >> 12;
    const int chunk = bid & 63;

    uint32_t smem_u32;
    asm("{ .reg .u64 t; cvta.to.shared.u64 t, %1; cvt.u32.u64 %0, t; }"
        : "=r"(smem_u32) : "l"(sm));

    // stage X [512][64] via cp.async
    {
        const float* Xb = X + (size_t)b*DD*NN + (n0 & (NN - 1));
        #pragma unroll
        for (int it = 0; it < 8; it++) {
            int idx = tid + it*1024;
            int row = idx >> 4, c4 = idx & 15;
            uint32_t dst = smem_u32 + K2_XS + (uint32_t)(row*64 + c4*4)*4u;
            const float* src = Xb + (size_t)row*NN + c4*4;
            asm volatile("cp.async.ca.shared.global [%0], [%1], 16;" :: "r"(dst), "l"(src));
        }
        asm volatile("cp.async.commit_group;");
    }
    // stage Q packed: Qsp[np][k] = (Q[2np][k], Q[2np+1][k])
    {
        const float* Qg = out + ZSIZE + (size_t)n0*KK;
        ull* Qsp = (ull*)(sm + K2_QS);
        if (tid < 256) {
            int np = tid >> 3, kq = tid & 7;
            float4 qa = *(const float4*)(Qg + (size_t)(2*np    )*KK + kq*4);
            float4 qb = *(const float4*)(Qg + (size_t)(2*np + 1)*KK + kq*4);
            Qsp[np*32 + kq*4 + 0] = pk2(qa.x, qb.x);
            Qsp[np*32 + kq*4 + 1] = pk2(qa.y, qb.y);
            Qsp[np*32 + kq*4 + 2] = pk2(qa.z, qb.z);
            Qsp[np*32 + kq*4 + 3] = pk2(qa.w, qb.w);
        }
    }
    asm volatile("cp.async.wait_group 0;");
    __syncthreads();

    {
        const float* Xs2 = (const float*)(sm + K2_XS);
        const ull*   Qsp = (const ull*)(sm + K2_QS);
        const int dbase = w*16;

        ull acc2[16];
        #pragma unroll
        for (int i = 0; i < 16; i++) acc2[i] = 0ull;

        #pragma unroll 1
        for (int ng = 0; ng < 4; ng++) {
            ull q2[8];
            #pragma unroll
            for (int j = 0; j < 8; j++)
                q2[j] = Qsp[(ng*8 + j)*32 + lane];
            #pragma unroll
            for (int dl = 0; dl < 16; dl++) {
                const float* xr = &Xs2[(dbase + dl)*64 + ng*16];
                longlong2 xa = *(const longlong2*)(xr);
                longlong2 xb = *(const longlong2*)(xr + 4);
                longlong2 xc = *(const longlong2*)(xr + 8);
                longlong2 xd = *(const longlong2*)(xr + 12);
                ull a = acc2[dl];
                a = fma2(q2[0], (ull)xa.x, a);
                a = fma2(q2[1], (ull)xa.y, a);
                a = fma2(q2[2], (ull)xb.x, a);
                a = fma2(q2[3], (ull)xb.y, a);
                a = fma2(q2[4], (ull)xc.x, a);
                a = fma2(q2[5], (ull)xc.y, a);
                a = fma2(q2[6], (ull)xd.x, a);
                a = fma2(q2[7], (ull)xd.y, a);
                acc2[dl] = a;
            }
        }
        float* dstc = g_M2 + (size_t)(b*64 + chunk)*DD*KK;
        #pragma unroll
        for (int dl = 0; dl < 16; dl++) {
            float lo, hi; upk2(acc2[dl], lo, hi);
            dstc[(dbase + dl)*KK + lane] = lo + hi;
        }
    }
}

// ============ K3: finalize1 — S1, M reduce, Z, sumsq. grid 128 x 1024 ============
__global__ __launch_bounds__(1024) void fin1_kernel(const float* __restrict__ scale,
                                                    const float* __restrict__ cw,
                                                    float* __restrict__ out) {
    __shared__ float redM[32*33];
    __shared__ float redS[32*33];
    __shared__ float cwf[32*9];
    __shared__ float bsh[KK];

    const int tid  = threadIdx.x;
    const int lane = tid & 31;
    const int w    = tid >> 5;
    const int bid  = blockIdx.x;
    const int bf  = bid >> 6;
    const int dtf = bid & 63;
    const int d0f = dtf*8;
    const int wd8 = w & 7, cg = w >> 3;
    const int dfw = d0f + wd8;
    const size_t mi = ((size_t)bf*DD + dfw)*KK + lane;

    if (tid < 256) {
        int k = tid >> 3, dl = tid & 7;
        cwf[k*9 + dl] = cw[k*DD + d0f + dl];
    }
    // M partial: warp (cg,wd8) sums 16 of 64 chunks for d = dfw
    float mp = 0.f;
    const float* msrc = g_M2 + (size_t)bf*64*DD*KK + (size_t)dfw*KK + lane;
    #pragma unroll
    for (int j = 0; j < 16; j++)
        mp += msrc[(size_t)(cg*16 + j)*DD*KK];
    redM[w*33 + lane] = mp;

    float s1p = g_S1part[(bf*64 + w)*KK + lane]
              + g_S1part[(bf*64 + 32 + w)*KK + lane];
    redS[w*33 + lane] = s1p;
    __syncthreads();
    if (w == 0) {
        float s = 0.f;
        #pragma unroll
        for (int i = 0; i < 32; i++) s += redS[i*33 + lane];
        bsh[lane] = 1.f / s;
    }
    __syncthreads();
    float z = 0.f;
    if (w < 8) {
        float m = redM[w*33 + lane] + redM[(8+w)*33 + lane]
                + redM[(16+w)*33 + lane] + redM[(24+w)*33 + lane];
        z = scale[dfw*KK + lane] * (m*bsh[lane] - cwf[lane*9 + w]);
        out[mi] = z;
    }
    __syncthreads();
    if (w < 8) redM[w*33 + lane] = z*z;
    __syncthreads();
    if (w == 0) {
        float s = 0.f;
        #pragma unroll
        for (int i = 0; i < 8; i++) s += redM[i*33 + lane];
        g_SS[(bf*64 + dtf)*KK + lane] = s;
    }
}

// ============ K4: rescale. grid 8 x 512 ============
__global__ __launch_bounds__(512) void fin2_kernel(float* __restrict__ out) {
    __shared__ float bsh[KK];
    const int b = blockIdx.x >> 2, q = blockIdx.x & 3;
    const int tid = threadIdx.x;

    if (tid < 32) {
        float s = 0.f;
        #pragma unroll
        for (int i = 0; i < 64; i++) s += g_SS[(b*64 + i)*KK + tid];
        bsh[tid] = rsqrtf(s);
    }
    __syncthreads();
    #pragma unroll
    for (int j = 0; j < 8; j++) {
        int idx = tid + j*512;               // 0..4095
        int d = q*128 + (idx >> 5), k = idx & 31;
        out[((size_t)b*DD + d)*KK + k] *= bsh[k];
    }
}

extern "C" void kernel_launch(void* const* d_in, const int* in_sizes, int n_in,
                              void* d_out, int out_size) {
    const float* X     = (const float*)d_in[0];
    const float* cw    = (const float*)d_in[1];
    const float* scale = (const float*)d_in[2];
    float* out = (float*)d_out;

    cudaFuncSetAttribute(assign_kernel, cudaFuncAttributeMaxDynamicSharedMemorySize,
                         SMEM_K1);
    cudaFuncSetAttribute(aggregate_kernel, cudaFuncAttributeMaxDynamicSharedMemorySize,
                         SMEM_K2);

    prep_kernel<<<32, 512>>>(scale, cw);
    assign_kernel<<<128, 1024, SMEM_K1>>>(X, out);
    aggregate_kernel<<<128, 1024, SMEM_K2>>>(X, out);
    fin1_kernel<<<128, 1024>>>(scale, cw, out);
    fin2_kernel<<<8, 512>>>(out);
}